// round 6
// baseline (speedup 1.0000x reference)
#include <cuda_runtime.h>

#define Bn      128
#define DMODEL  1024
#define DMEM    64
#define NH      16
#define NMEM    4096

typedef unsigned long long u64;

__device__ __forceinline__ u64 ffma2(u64 a, u64 b, u64 c) {
    u64 d;
    asm("fma.rn.f32x2 %0, %1, %2, %3;" : "=l"(d) : "l"(a), "l"(b), "l"(c));
    return d;
}

// ---- scratch (__device__ globals; no allocation allowed) ----
__device__ float g_qa[Bn * DMODEL];          // relu(query @ Wq^T + bq)
__device__ float g_mat[Bn * DMEM * DMEM];    // per-batch 64x64 kernel matrix
__device__ float g_norm[Bn * DMEM];          // per-batch normalizer
__device__ float g_attn[Bn * DMODEL];        // attention output
__device__ float g_gp[4 * Bn * DMODEL];      // split-K GEMM partials (2 MB)

// ============================================================
// Stage 1: matrix[b] = relu(mem[b]+addr)^T @ mem[b], norm[b] = sum_n k
// One block per batch, 256 threads, 4x4 tile/thread (pairs along e).
// k stored PRE-DUPLICATED as (k,k) pairs in smem -> no pack MOVs in
// the inner loop: 3 LDS + 8 ffma2 per n per thread.
// ============================================================
#define CN 32
#define NCHUNK (NMEM / CN)

__global__ __launch_bounds__(256) void stage1_kernel(
    const float* __restrict__ mem, const float* __restrict__ addr)
{
    __shared__ float s_kd[2][CN][2 * DMEM];  // duplicated k pairs (32 KB)
    __shared__ float s_m [2][CN][DMEM];      // raw memories       (16 KB)

    const int b   = blockIdx.x;
    const int tid = threadIdx.x;
    const int tx  = tid & 15;                // e-tile: e = 4*tx
    const int ty  = tid >> 4;                // d-tile: d = 4*ty
    const int lc  = tx * 4;                  // load column

    const float* mb = mem + (size_t)b * NMEM * DMEM;

    u64 acc[4][2];
#pragma unroll
    for (int i = 0; i < 4; i++) { acc[i][0] = 0ull; acc[i][1] = 0ull; }
    float4 nacc = make_float4(0.f, 0.f, 0.f, 0.f);

    float4 rm[2], ra[2];

    auto ldg_chunk = [&](int ch) {
        const float* pm = mb   + ((size_t)ch * CN + ty) * DMEM + lc;
        const float* pa = addr + ((size_t)ch * CN + ty) * DMEM + lc;
        rm[0] = *(const float4*)pm;
        rm[1] = *(const float4*)(pm + 16 * DMEM);
        ra[0] = *(const float4*)pa;
        ra[1] = *(const float4*)(pa + 16 * DMEM);
    };
    auto sts_chunk = [&](int buf) {
#pragma unroll
        for (int h = 0; h < 2; h++) {
            int r = ty + 16 * h;
            float4 m4 = rm[h], a4 = ra[h], k4;
            k4.x = fmaxf(m4.x + a4.x, 0.f);
            k4.y = fmaxf(m4.y + a4.y, 0.f);
            k4.z = fmaxf(m4.z + a4.z, 0.f);
            k4.w = fmaxf(m4.w + a4.w, 0.f);
            *(float4*)&s_m[buf][r][lc] = m4;
            *(float4*)&s_kd[buf][r][2 * lc]     = make_float4(k4.x, k4.x, k4.y, k4.y);
            *(float4*)&s_kd[buf][r][2 * lc + 4] = make_float4(k4.z, k4.z, k4.w, k4.w);
            nacc.x += k4.x; nacc.y += k4.y; nacc.z += k4.z; nacc.w += k4.w;
        }
    };

    ldg_chunk(0);
    sts_chunk(0);
    __syncthreads();

    for (int ch = 0; ch < NCHUNK; ch++) {
        const int cur = ch & 1;
        if (ch + 1 < NCHUNK) ldg_chunk(ch + 1);

#pragma unroll 8
        for (int n = 0; n < CN; n++) {
            ulonglong2 kd01 = *(const ulonglong2*)&s_kd[cur][n][ty * 8];
            ulonglong2 kd23 = *(const ulonglong2*)&s_kd[cur][n][ty * 8 + 4];
            ulonglong2 mv   = *(const ulonglong2*)&s_m [cur][n][tx * 4];
            acc[0][0] = ffma2(kd01.x, mv.x, acc[0][0]);
            acc[0][1] = ffma2(kd01.x, mv.y, acc[0][1]);
            acc[1][0] = ffma2(kd01.y, mv.x, acc[1][0]);
            acc[1][1] = ffma2(kd01.y, mv.y, acc[1][1]);
            acc[2][0] = ffma2(kd23.x, mv.x, acc[2][0]);
            acc[2][1] = ffma2(kd23.x, mv.y, acc[2][1]);
            acc[3][0] = ffma2(kd23.y, mv.x, acc[3][0]);
            acc[3][1] = ffma2(kd23.y, mv.y, acc[3][1]);
        }
        __syncthreads();
        if (ch + 1 < NCHUNK) {
            sts_chunk((ch + 1) & 1);
            __syncthreads();
        }
    }

    // matrix tile (acc pairs are (e, e+1); low word = first element)
    float* om = g_mat + (size_t)b * DMEM * DMEM + (ty * 4) * DMEM + tx * 4;
#pragma unroll
    for (int i = 0; i < 4; i++) {
        ulonglong2 v;
        v.x = acc[i][0];
        v.y = acc[i][1];
        *(ulonglong2*)(om + i * DMEM) = v;
    }

    // normalizer reduce (alias scratch onto s_kd; last compute already synced)
    float* s_np = (float*)s_kd;              // need 16*64 floats = 4 KB
    ((float4*)s_np)[ty * 16 + tx] = nacc;    // s_np[ty*64 + lc]
    __syncthreads();
    if (tid < DMEM) {
        float s = 0.f;
#pragma unroll
        for (int g = 0; g < 16; g++) s += s_np[g * DMEM + tid];
        g_norm[b * DMEM + tid] = s;
    }
}

// ============================================================
// Split-K NT GEMM partials: P[ks] += A[128,1024] @ W[1024,1024]^T chunk
// grid (16 n-tiles, 2 m-tiles, 4 k-splits) = 128 blocks, 256 threads.
// 64x64 tile, 4x4/thread, f32x2 with A pre-duplicated in smem.
// mode: 0 -> A = A_ext (query); 1 -> A = g_attn
// ============================================================
__global__ __launch_bounds__(256) void gemm_part(
    const float* __restrict__ A_ext, const float* __restrict__ W, int mode)
{
    __shared__ float Asd[32][132];   // duplicated A pairs, padded (16.5 KB)
    __shared__ float Bs [32][68];    // W tile, padded (8.5 KB)

    const float* A = (mode == 0) ? A_ext : g_attn;

    const int tid = threadIdx.x;
    const int tx  = tid & 15;            // n: 4*tx
    const int ty  = tid >> 4;            // m: 4*ty
    const int bn  = blockIdx.x * 64;
    const int bm  = blockIdx.y * 64;
    const int ks  = blockIdx.z;
    const int r0  = tid >> 3;            // 0..31 (load row)
    const int c0  = (tid & 7) * 4;       // 0..28 (load k-col within chunk)

    u64 acc[4][2];
#pragma unroll
    for (int i = 0; i < 4; i++) { acc[i][0] = 0ull; acc[i][1] = 0ull; }

    float4 pa[2], pw[2];
    auto ldg = [&](int k0) {
        pa[0] = *(const float4*)(A + (size_t)(bm + r0)      * DMODEL + k0 + c0);
        pa[1] = *(const float4*)(A + (size_t)(bm + r0 + 32) * DMODEL + k0 + c0);
        pw[0] = *(const float4*)(W + (size_t)(bn + r0)      * DMODEL + k0 + c0);
        pw[1] = *(const float4*)(W + (size_t)(bn + r0 + 32) * DMODEL + k0 + c0);
    };

    ldg(ks * 256);
    for (int ck = 0; ck < 8; ck++) {
        __syncthreads();
#pragma unroll
        for (int h = 0; h < 2; h++) {
            int r = r0 + 32 * h;
            float am[4] = {pa[h].x, pa[h].y, pa[h].z, pa[h].w};
            float wm[4] = {pw[h].x, pw[h].y, pw[h].z, pw[h].w};
#pragma unroll
            for (int j = 0; j < 4; j++) {
                *(float2*)&Asd[c0 + j][2 * r] = make_float2(am[j], am[j]);
                Bs[c0 + j][r] = wm[j];
            }
        }
        __syncthreads();
        if (ck + 1 < 8) ldg(ks * 256 + (ck + 1) * 32);

#pragma unroll 8
        for (int k = 0; k < 32; k++) {
            ulonglong2 a01 = *(const ulonglong2*)&Asd[k][ty * 8];
            ulonglong2 a23 = *(const ulonglong2*)&Asd[k][ty * 8 + 4];
            ulonglong2 bv  = *(const ulonglong2*)&Bs[k][tx * 4];
            acc[0][0] = ffma2(a01.x, bv.x, acc[0][0]);
            acc[0][1] = ffma2(a01.x, bv.y, acc[0][1]);
            acc[1][0] = ffma2(a01.y, bv.x, acc[1][0]);
            acc[1][1] = ffma2(a01.y, bv.y, acc[1][1]);
            acc[2][0] = ffma2(a23.x, bv.x, acc[2][0]);
            acc[2][1] = ffma2(a23.x, bv.y, acc[2][1]);
            acc[3][0] = ffma2(a23.y, bv.x, acc[3][0]);
            acc[3][1] = ffma2(a23.y, bv.y, acc[3][1]);
        }
    }

    float* P = g_gp + (size_t)ks * Bn * DMODEL
                    + (size_t)(bm + ty * 4) * DMODEL + bn + tx * 4;
#pragma unroll
    for (int i = 0; i < 4; i++) {
        ulonglong2 v;
        v.x = acc[i][0];
        v.y = acc[i][1];
        *(ulonglong2*)(P + (size_t)i * DMODEL) = v;
    }
}

// reduce 4 split-K partials + bias (+relu); C = g_qa (mode 0) or ext (mode 1)
__global__ __launch_bounds__(256) void gemm_reduce(
    const float* __restrict__ bias, float* __restrict__ C_ext, int mode)
{
    int idx = blockIdx.x * 256 + threadIdx.x;     // 512 blocks -> 131072
    int n = idx & (DMODEL - 1);
    float v = g_gp[idx] + g_gp[Bn * DMODEL + idx]
            + g_gp[2 * Bn * DMODEL + idx] + g_gp[3 * Bn * DMODEL + idx]
            + bias[n];
    if (mode == 0) {
        g_qa[idx] = fmaxf(v, 0.f);
    } else {
        C_ext[idx] = v;
    }
}

// ============================================================
// Stage 2 read: attn[b,h,:] = (qa[b,h,:] @ matrix[b]) / (qa.norm + 1e-5)
// ============================================================
__global__ __launch_bounds__(64) void attn_read_kernel()
{
    __shared__ float s_q[DMEM];
    __shared__ float s_d[2];

    const int h = blockIdx.x;
    const int b = blockIdx.y;
    const int e = threadIdx.x;

    float qv = g_qa[(size_t)b * DMODEL + h * DMEM + e];   // already relu'd
    s_q[e] = qv;

    float p = qv * g_norm[b * DMEM + e];
#pragma unroll
    for (int o = 16; o > 0; o >>= 1) p += __shfl_down_sync(0xffffffffu, p, o);
    if ((e & 31) == 0) s_d[e >> 5] = p;
    __syncthreads();
    float denom = s_d[0] + s_d[1] + 1e-5f;

    const float* mrow = g_mat + (size_t)b * DMEM * DMEM;
    float acc = 0.f;
#pragma unroll 8
    for (int d = 0; d < DMEM; d++) acc += s_q[d] * mrow[d * DMEM + e];

    g_attn[(size_t)b * DMODEL + h * DMEM + e] = acc / denom;
}

// ============================================================
extern "C" void kernel_launch(void* const* d_in, const int* in_sizes, int n_in,
                              void* d_out, int out_size)
{
    (void)in_sizes; (void)n_in; (void)out_size;
    const float* query     = (const float*)d_in[0];
    const float* addresses = (const float*)d_in[1];
    const float* memories  = (const float*)d_in[2];
    const float* Wq        = (const float*)d_in[3];
    const float* bq        = (const float*)d_in[4];
    const float* Wm        = (const float*)d_in[5];
    const float* bm        = (const float*)d_in[6];
    float* out = (float*)d_out;

    // qa = relu(query @ Wq^T + bq)
    gemm_part<<<dim3(16, 2, 4), 256>>>(query, Wq, 0);
    gemm_reduce<<<512, 256>>>(bq, nullptr, 0);
    // matrix / normalizer
    stage1_kernel<<<Bn, 256>>>(memories, addresses);
    // attn
    attn_read_kernel<<<dim3(NH, Bn), 64>>>();
    // out = attn @ Wm^T + bm
    gemm_part<<<dim3(16, 2, 4), 256>>>(nullptr, Wm, 1);
    gemm_reduce<<<512, 256>>>(bm, out, 1);
}

// round 9
// speedup vs baseline: 2.0631x; 2.0631x over previous
#include <cuda_runtime.h>
#include <cuda_bf16.h>
#include <cstdint>

#define Bn      128
#define DMODEL  1024
#define DMEM    64
#define NH      16
#define NMEM    4096

// ================= helpers =================
__device__ __forceinline__ uint32_t smem_u32(const void* p) {
    uint32_t a;
    asm("{ .reg .u64 t; cvta.to.shared.u64 t, %1; cvt.u32.u64 %0, t; }"
        : "=r"(a) : "l"(p));
    return a;
}
__device__ __forceinline__ void ldsm4(uint32_t* r, uint32_t a) {
    asm volatile("ldmatrix.sync.aligned.m8n8.x4.shared.b16 {%0,%1,%2,%3}, [%4];"
                 : "=r"(r[0]), "=r"(r[1]), "=r"(r[2]), "=r"(r[3]) : "r"(a));
}
__device__ __forceinline__ void ldsm4t(uint32_t* r, uint32_t a) {
    asm volatile("ldmatrix.sync.aligned.m8n8.x4.trans.shared.b16 {%0,%1,%2,%3}, [%4];"
                 : "=r"(r[0]), "=r"(r[1]), "=r"(r[2]), "=r"(r[3]) : "r"(a));
}
__device__ __forceinline__ void mma16816(float* c, const uint32_t* a,
                                         uint32_t b0, uint32_t b1) {
    asm volatile(
        "mma.sync.aligned.m16n8k16.row.col.f32.bf16.bf16.f32 "
        "{%0,%1,%2,%3}, {%4,%5,%6,%7}, {%8,%9}, {%0,%1,%2,%3};"
        : "+f"(c[0]), "+f"(c[1]), "+f"(c[2]), "+f"(c[3])
        : "r"(a[0]), "r"(a[1]), "r"(a[2]), "r"(a[3]), "r"(b0), "r"(b1));
}
__device__ __forceinline__ unsigned b2u(__nv_bfloat162 v) {
    return *reinterpret_cast<unsigned*>(&v);
}
// split a float2 into bf16x2 hi + bf16x2 lo (residual)
__device__ __forceinline__ void split2(float2 f, uint32_t& hi, uint32_t& lo) {
    __nv_bfloat162 h = __float22bfloat162_rn(f);
    float2 hf = __bfloat1622float2(h);
    __nv_bfloat162 l = __float22bfloat162_rn(make_float2(f.x - hf.x, f.y - hf.y));
    hi = b2u(h);
    lo = b2u(l);
}

// ================= scratch =================
__device__ float g_qa[Bn * DMODEL];
__device__ float g_mat[Bn * DMEM * DMEM];
__device__ float g_norm[Bn * DMEM];
__device__ float g_attn[Bn * DMODEL];
__device__ float g_gp[8 * Bn * DMODEL];      // split-K partials (4 MB)

// ============================================================
// Stage 1 (HMMA): per batch b,
//   matrix[d][e] = sum_n relu(mem+addr)[n][d] * mem[n][e]
//   norm[d]      = sum_n k[n][d]
// smem tiles [n=64][feat=64] bf16 (kh,kl,mh,ml), 128B rows, XOR-swizzled.
// A (k^T) and B (m^T col-major) both via ldmatrix.x4.trans.
// 8 warps: warp w -> d rows 16*(w&3), e cols 32*(w>>2).
// ============================================================
#define S1_SMEM 32768

__global__ __launch_bounds__(256, 1) void stage1_mma(
    const float* __restrict__ mem, const float* __restrict__ addr)
{
    extern __shared__ __align__(1024) char sm[];
    const uint32_t sb = smem_u32(sm);
    const int b = blockIdx.x, tid = threadIdx.x;
    const int lane = tid & 31, w = tid >> 5;

    // tile byte offsets inside smem
    const uint32_t KH = 0, KL = 8192, MH = 16384, ML = 24576;

    // ---- conversion-phase mapping: thread -> (n row, 16-float d group) ----
    const int n1 = tid >> 2;
    const int dg = (tid & 3) << 4;
    const uint32_t cmask = (uint32_t)(n1 & 7) << 4;
    const uint32_t sw0 = ((uint32_t)(n1 * 128 + dg * 2)) ^ cmask;        // chunk 0 (16B)
    const uint32_t sw1 = ((uint32_t)(n1 * 128 + dg * 2 + 16)) ^ cmask;   // chunk 1

    // ---- mma-phase lane offsets (swizzled, tile-relative) ----
    const int m0 = (w & 3) * 16;          // d rows
    const int e0 = (w >> 2) * 32;         // e cols
    const uint32_t lm = (uint32_t)(lane & 7) << 4;
    const int rA = (lane & 7) + 8 * (lane >> 4);
    const int cA = m0 + 8 * ((lane >> 3) & 1);
    const uint32_t swA = ((uint32_t)(rA * 128 + cA * 2)) ^ lm;
    const int rB = (lane & 7) + 8 * ((lane >> 3) & 1);
    const int cB = e0 + 8 * (lane >> 4);
    const uint32_t swB0 = ((uint32_t)(rB * 128 + cB * 2)) ^ lm;
    const uint32_t swB1 = ((uint32_t)(rB * 128 + (cB + 16) * 2)) ^ lm;

    float acc[4][4];
#pragma unroll
    for (int i = 0; i < 4; i++)
#pragma unroll
        for (int j = 0; j < 4; j++) acc[i][j] = 0.f;

    float nacc[16];
#pragma unroll
    for (int i = 0; i < 16; i++) nacc[i] = 0.f;

    const float* mb = mem + (size_t)b * NMEM * DMEM;

    float4 m4[4], a4[4];
    auto ldg_chunk = [&](int ch) {
        const float* pm = mb   + ((size_t)ch * 64 + n1) * DMEM + dg;
        const float* pa = addr + ((size_t)ch * 64 + n1) * DMEM + dg;
#pragma unroll
        for (int j = 0; j < 4; j++) {
            m4[j] = *(const float4*)(pm + 4 * j);
            a4[j] = *(const float4*)(pa + 4 * j);
        }
    };

    ldg_chunk(0);

    for (int ch = 0; ch < NMEM / 64; ch++) {
        // ---- convert + store tiles (single buffer; safe: store after compute sync) ----
        {
            float mv[16], kv[16];
#pragma unroll
            for (int j = 0; j < 4; j++) {
                mv[4*j+0] = m4[j].x; mv[4*j+1] = m4[j].y;
                mv[4*j+2] = m4[j].z; mv[4*j+3] = m4[j].w;
                kv[4*j+0] = fmaxf(m4[j].x + a4[j].x, 0.f);
                kv[4*j+1] = fmaxf(m4[j].y + a4[j].y, 0.f);
                kv[4*j+2] = fmaxf(m4[j].z + a4[j].z, 0.f);
                kv[4*j+3] = fmaxf(m4[j].w + a4[j].w, 0.f);
            }
#pragma unroll
            for (int i = 0; i < 16; i++) nacc[i] += kv[i];
#pragma unroll
            for (int g = 0; g < 2; g++) {
                uint32_t kh[4], kl[4], mh[4], ml[4];
#pragma unroll
                for (int p = 0; p < 4; p++) {
                    split2(make_float2(kv[8*g+2*p], kv[8*g+2*p+1]), kh[p], kl[p]);
                    split2(make_float2(mv[8*g+2*p], mv[8*g+2*p+1]), mh[p], ml[p]);
                }
                uint32_t sw = g ? sw1 : sw0;
                *(uint4*)(sm + KH + sw) = make_uint4(kh[0], kh[1], kh[2], kh[3]);
                *(uint4*)(sm + KL + sw) = make_uint4(kl[0], kl[1], kl[2], kl[3]);
                *(uint4*)(sm + MH + sw) = make_uint4(mh[0], mh[1], mh[2], mh[3]);
                *(uint4*)(sm + ML + sw) = make_uint4(ml[0], ml[1], ml[2], ml[3]);
            }
        }
        __syncthreads();

        if (ch + 1 < NMEM / 64) ldg_chunk(ch + 1);   // overlap LDG with mma

        // ---- mma phase: 4 ksteps x (2 A-ldsm + 4 B-ldsm + 12 mma) ----
#pragma unroll
        for (int ks = 0; ks < 4; ks++) {
            const uint32_t ko = 2048u * ks;
            uint32_t ah[4], al[4], bh0[4], bh1[4], bl0[4], bl1[4];
            ldsm4t(ah,  sb + KH + swA + ko);
            ldsm4t(al,  sb + KL + swA + ko);
            ldsm4t(bh0, sb + MH + swB0 + ko);
            ldsm4t(bh1, sb + MH + swB1 + ko);
            ldsm4t(bl0, sb + ML + swB0 + ko);
            ldsm4t(bl1, sb + ML + swB1 + ko);
            // hi*hi
            mma16816(acc[0], ah, bh0[0], bh0[1]);
            mma16816(acc[1], ah, bh0[2], bh0[3]);
            mma16816(acc[2], ah, bh1[0], bh1[1]);
            mma16816(acc[3], ah, bh1[2], bh1[3]);
            // hi*lo
            mma16816(acc[0], ah, bl0[0], bl0[1]);
            mma16816(acc[1], ah, bl0[2], bl0[3]);
            mma16816(acc[2], ah, bl1[0], bl1[1]);
            mma16816(acc[3], ah, bl1[2], bl1[3]);
            // lo*hi
            mma16816(acc[0], al, bh0[0], bh0[1]);
            mma16816(acc[1], al, bh0[2], bh0[3]);
            mma16816(acc[2], al, bh1[0], bh1[1]);
            mma16816(acc[3], al, bh1[2], bh1[3]);
        }
        __syncthreads();
    }

    // ---- write matrix: C frag layout row=lane>>2(+8), col=(lane&3)*2 ----
    {
        float* om = g_mat + (size_t)b * DMEM * DMEM;
        int r0 = m0 + (lane >> 2);
        int c0 = e0 + (lane & 3) * 2;
#pragma unroll
        for (int j = 0; j < 4; j++) {
            int c = c0 + 8 * j;
            *(float2*)(om + (size_t)r0 * DMEM + c)       = make_float2(acc[j][0], acc[j][1]);
            *(float2*)(om + (size_t)(r0 + 8) * DMEM + c) = make_float2(acc[j][2], acc[j][3]);
        }
    }

    // ---- normalizer reduce via smem scratch (tiles dead; stride 65 = conflict-free) ----
    float* scr = (float*)sm;
#pragma unroll
    for (int i = 0; i < 16; i++) scr[n1 * 65 + dg + i] = nacc[i];
    __syncthreads();
    if (tid < DMEM) {
        float s = 0.f;
#pragma unroll 8
        for (int n = 0; n < 64; n++) s += scr[n * 65 + tid];
        g_norm[b * DMEM + tid] = s;
    }
}

// ============================================================
// HMMA split-K NT GEMM: P[kt] = A[128,1024] @ W[1024,1024]^T chunk
// grid (16 n-tiles, 8 k-splits) = 128 blocks. Block: m=128 full, n=64,
// k-chunk 128. A row-major and W row-major need NO transposes.
// smem: Ah/Al 32KB each, Wh/Wl 16KB each (96KB, dynamic).
// ============================================================
#define GA_H 0
#define GA_L 32768
#define GW_H 65536
#define GW_L 81920
#define G_SMEM 98304

__global__ __launch_bounds__(256, 1) void gemm_mma(
    const float* __restrict__ A_ext, const float* __restrict__ W, int mode)
{
    extern __shared__ __align__(1024) char sm[];
    const uint32_t sb = smem_u32(sm);
    const float* A = mode ? g_attn : A_ext;

    const int tid = threadIdx.x, lane = tid & 31, w = tid >> 5;
    const int bn = blockIdx.x * 64;
    const int kc0 = blockIdx.y * 128;

    // ---- convert A chunk [128 x 128] ----
#pragma unroll
    for (int i = 0; i < 8; i++) {
        int item = tid + 256 * i;
        int row = item >> 4, c8 = item & 15;
        const float* p = A + (size_t)row * DMODEL + kc0 + c8 * 8;
        float4 f0 = *(const float4*)p, f1 = *(const float4*)(p + 4);
        uint32_t h[4], l[4];
        split2(make_float2(f0.x, f0.y), h[0], l[0]);
        split2(make_float2(f0.z, f0.w), h[1], l[1]);
        split2(make_float2(f1.x, f1.y), h[2], l[2]);
        split2(make_float2(f1.z, f1.w), h[3], l[3]);
        uint32_t off = (uint32_t)(row * 256 + c8 * 16);
        uint32_t sw = off ^ ((off >> 4) & 0x70);
        *(uint4*)(sm + GA_H + sw) = make_uint4(h[0], h[1], h[2], h[3]);
        *(uint4*)(sm + GA_L + sw) = make_uint4(l[0], l[1], l[2], l[3]);
    }
    // ---- convert W chunk [64 x 128] ----
#pragma unroll
    for (int i = 0; i < 4; i++) {
        int item = tid + 256 * i;
        int row = item >> 4, c8 = item & 15;
        const float* p = W + (size_t)(bn + row) * DMODEL + kc0 + c8 * 8;
        float4 f0 = *(const float4*)p, f1 = *(const float4*)(p + 4);
        uint32_t h[4], l[4];
        split2(make_float2(f0.x, f0.y), h[0], l[0]);
        split2(make_float2(f0.z, f0.w), h[1], l[1]);
        split2(make_float2(f1.x, f1.y), h[2], l[2]);
        split2(make_float2(f1.z, f1.w), h[3], l[3]);
        uint32_t off = (uint32_t)(row * 256 + c8 * 16);
        uint32_t sw = off ^ ((off >> 4) & 0x70);
        *(uint4*)(sm + GW_H + sw) = make_uint4(h[0], h[1], h[2], h[3]);
        *(uint4*)(sm + GW_L + sw) = make_uint4(l[0], l[1], l[2], l[3]);
    }
    __syncthreads();

    // ---- mma: warp w owns m rows 16w, all 64 n ----
    const int m0 = w * 16;
    float acc[8][4];
#pragma unroll
    for (int i = 0; i < 8; i++)
#pragma unroll
        for (int j = 0; j < 4; j++) acc[i][j] = 0.f;

    const int rA = (lane & 7) + 8 * ((lane >> 3) & 1);
    const uint32_t baseA = (uint32_t)((m0 + rA) * 256 + (lane >> 4) * 16);
    const uint32_t maskA = (uint32_t)(lane & 7) << 4;
    const int rBl = (lane & 7) + 8 * (lane >> 4);
    const uint32_t hB = ((uint32_t)(lane >> 3) & 1) * 16;
    const uint32_t maskB = (uint32_t)(lane & 7) << 4;

#pragma unroll
    for (int ks = 0; ks < 8; ks++) {
        uint32_t swAa = (baseA + ks * 32) ^ maskA;
        uint32_t ah[4], al[4];
        ldsm4(ah, sb + GA_H + swAa);
        ldsm4(al, sb + GA_L + swAa);
#pragma unroll
        for (int j = 0; j < 4; j++) {
            uint32_t offB = (uint32_t)((16 * j + rBl) * 256 + ks * 32) + hB;
            uint32_t swB = offB ^ maskB;
            uint32_t wh[4], wl[4];
            ldsm4(wh, sb + GW_H + swB);
            ldsm4(wl, sb + GW_L + swB);
            mma16816(acc[2*j],     ah, wh[0], wh[1]);
            mma16816(acc[2*j + 1], ah, wh[2], wh[3]);
            mma16816(acc[2*j],     ah, wl[0], wl[1]);
            mma16816(acc[2*j + 1], ah, wl[2], wl[3]);
            mma16816(acc[2*j],     al, wh[0], wh[1]);
            mma16816(acc[2*j + 1], al, wh[2], wh[3]);
        }
    }

    // ---- write partials ----
    float* P = g_gp + (size_t)blockIdx.y * (Bn * DMODEL);
    int r0 = m0 + (lane >> 2);
    int c0 = bn + (lane & 3) * 2;
#pragma unroll
    for (int jj = 0; jj < 8; jj++) {
        int c = c0 + 8 * jj;
        *(float2*)(P + (size_t)r0 * DMODEL + c)       = make_float2(acc[jj][0], acc[jj][1]);
        *(float2*)(P + (size_t)(r0 + 8) * DMODEL + c) = make_float2(acc[jj][2], acc[jj][3]);
    }
}

// reduce 8 split-K partials + bias (+relu for mode 0)
__global__ __launch_bounds__(256) void gemm_reduce(
    const float* __restrict__ bias, float* __restrict__ C_ext, int mode)
{
    int idx = blockIdx.x * 256 + threadIdx.x;
    float v = bias[idx & (DMODEL - 1)];
#pragma unroll
    for (int s = 0; s < 8; s++) v += g_gp[(size_t)s * Bn * DMODEL + idx];
    if (mode == 0) g_qa[idx] = fmaxf(v, 0.f);
    else           C_ext[idx] = v;
}

// ============================================================
// Stage 2 read: one block per batch, matrix smem-resident.
// ============================================================
__global__ __launch_bounds__(256) void attn_read_kernel()
{
    __shared__ float s_mat[DMEM * DMEM];
    __shared__ float s_q[NH * DMEM];
    __shared__ float s_n[DMEM];
    __shared__ float s_den[NH];

    const int b = blockIdx.x;
    const int tid = threadIdx.x;

    {
        float4* dst = (float4*)s_mat;
        const float4* src = (const float4*)(g_mat + (size_t)b * DMEM * DMEM);
#pragma unroll
        for (int i = 0; i < 4; i++) dst[tid + 256 * i] = src[tid + 256 * i];
        ((float4*)s_q)[tid] = ((const float4*)(g_qa + (size_t)b * DMODEL))[tid];
        if (tid < 16) ((float4*)s_n)[tid] = ((const float4*)(g_norm + b * DMEM))[tid];
    }
    __syncthreads();

    if (tid < NH) {
        float s = 0.f;
#pragma unroll 8
        for (int d = 0; d < DMEM; d++) s += s_q[tid * DMEM + d] * s_n[d];
        s_den[tid] = s + 1e-5f;
    }
    __syncthreads();

    const int e = tid & 63;
    const int hq = tid >> 6;
#pragma unroll
    for (int i = 0; i < 4; i++) {
        int h = hq * 4 + i;
        float acc = 0.f;
#pragma unroll 8
        for (int d = 0; d < DMEM; d++) acc += s_q[h * DMEM + d] * s_mat[d * DMEM + e];
        g_attn[(size_t)b * DMODEL + h * DMEM + e] = acc / s_den[h];
    }
}

// ============================================================
extern "C" void kernel_launch(void* const* d_in, const int* in_sizes, int n_in,
                              void* d_out, int out_size)
{
    (void)in_sizes; (void)n_in; (void)out_size;
    const float* query     = (const float*)d_in[0];
    const float* addresses = (const float*)d_in[1];
    const float* memories  = (const float*)d_in[2];
    const float* Wq        = (const float*)d_in[3];
    const float* bq        = (const float*)d_in[4];
    const float* Wm        = (const float*)d_in[5];
    const float* bm        = (const float*)d_in[6];
    float* out = (float*)d_out;

    static bool attr_set = false;
    if (!attr_set) {
        cudaFuncSetAttribute(gemm_mma, cudaFuncAttributeMaxDynamicSharedMemorySize, G_SMEM);
        attr_set = true;
    }

    // qa = relu(query @ Wq^T + bq)
    gemm_mma<<<dim3(16, 8), 256, G_SMEM>>>(query, Wq, 0);
    gemm_reduce<<<512, 256>>>(bq, nullptr, 0);
    // matrix / normalizer
    stage1_mma<<<Bn, 256, S1_SMEM>>>(memories, addresses);
    // attn
    attn_read_kernel<<<Bn, 256>>>();
    // out = attn @ Wm^T + bm
    gemm_mma<<<dim3(16, 8), 256, G_SMEM>>>(nullptr, Wm, 1);
    gemm_reduce<<<512, 256>>>(bm, out, 1);
}

// round 10
// speedup vs baseline: 2.0833x; 1.0098x over previous
#include <cuda_runtime.h>
#include <cuda_bf16.h>
#include <cstdint>

#define Bn      128
#define DMODEL  1024
#define DMEM    64
#define NH      16
#define NMEM    4096

// ================= helpers =================
__device__ __forceinline__ uint32_t smem_u32(const void* p) {
    uint32_t a;
    asm("{ .reg .u64 t; cvta.to.shared.u64 t, %1; cvt.u32.u64 %0, t; }"
        : "=r"(a) : "l"(p));
    return a;
}
__device__ __forceinline__ void ldsm4(uint32_t* r, uint32_t a) {
    asm volatile("ldmatrix.sync.aligned.m8n8.x4.shared.b16 {%0,%1,%2,%3}, [%4];"
                 : "=r"(r[0]), "=r"(r[1]), "=r"(r[2]), "=r"(r[3]) : "r"(a));
}
__device__ __forceinline__ void ldsm4t(uint32_t* r, uint32_t a) {
    asm volatile("ldmatrix.sync.aligned.m8n8.x4.trans.shared.b16 {%0,%1,%2,%3}, [%4];"
                 : "=r"(r[0]), "=r"(r[1]), "=r"(r[2]), "=r"(r[3]) : "r"(a));
}
__device__ __forceinline__ void mma16816(float* c, const uint32_t* a,
                                         uint32_t b0, uint32_t b1) {
    asm volatile(
        "mma.sync.aligned.m16n8k16.row.col.f32.bf16.bf16.f32 "
        "{%0,%1,%2,%3}, {%4,%5,%6,%7}, {%8,%9}, {%0,%1,%2,%3};"
        : "+f"(c[0]), "+f"(c[1]), "+f"(c[2]), "+f"(c[3])
        : "r"(a[0]), "r"(a[1]), "r"(a[2]), "r"(a[3]), "r"(b0), "r"(b1));
}
__device__ __forceinline__ unsigned b2u(__nv_bfloat162 v) {
    return *reinterpret_cast<unsigned*>(&v);
}
// split a float2 into bf16x2 hi + bf16x2 lo (residual)
__device__ __forceinline__ void split2(float2 f, uint32_t& hi, uint32_t& lo) {
    __nv_bfloat162 h = __float22bfloat162_rn(f);
    float2 hf = __bfloat1622float2(h);
    __nv_bfloat162 l = __float22bfloat162_rn(make_float2(f.x - hf.x, f.y - hf.y));
    hi = b2u(h);
    lo = b2u(l);
}

// ================= scratch =================
__device__ float g_qa[Bn * DMODEL];
__device__ float g_mat[Bn * DMEM * DMEM];
__device__ float g_norm[Bn * DMEM];
__device__ float g_attn[Bn * DMODEL];
__device__ float g_gp[8 * Bn * DMODEL];      // split-K partials (4 MB)

// ============================================================
// Stage 1 (HMMA): per batch b,
//   matrix[d][e] = sum_n relu(mem+addr)[n][d] * mem[n][e]
//   norm[d]      = sum_n k[n][d]
// smem tiles [n=64][feat=64] bf16 (kh,kl,mh,ml), 128B rows, XOR-swizzled.
// A (k^T) and B (m^T col-major) both via ldmatrix.x4.trans.
// 8 warps: warp w -> d rows 16*(w&3), e cols 32*(w>>2).
// ============================================================
#define S1_SMEM 32768

__global__ __launch_bounds__(256, 1) void stage1_mma(
    const float* __restrict__ mem, const float* __restrict__ addr)
{
    extern __shared__ __align__(1024) char sm[];
    const uint32_t sb = smem_u32(sm);
    const int b = blockIdx.x, tid = threadIdx.x;
    const int lane = tid & 31, w = tid >> 5;

    // tile byte offsets inside smem
    const uint32_t KH = 0, KL = 8192, MH = 16384, ML = 24576;

    // ---- conversion-phase mapping: thread -> (n row, 16-float d group) ----
    const int n1 = tid >> 2;
    const int dg = (tid & 3) << 4;
    const uint32_t cmask = (uint32_t)(n1 & 7) << 4;
    const uint32_t sw0 = ((uint32_t)(n1 * 128 + dg * 2)) ^ cmask;        // chunk 0 (16B)
    const uint32_t sw1 = ((uint32_t)(n1 * 128 + dg * 2 + 16)) ^ cmask;   // chunk 1

    // ---- mma-phase lane offsets (swizzled, tile-relative) ----
    const int m0 = (w & 3) * 16;          // d rows
    const int e0 = (w >> 2) * 32;         // e cols
    const uint32_t lm = (uint32_t)(lane & 7) << 4;
    const int rA = (lane & 7) + 8 * (lane >> 4);
    const int cA = m0 + 8 * ((lane >> 3) & 1);
    const uint32_t swA = ((uint32_t)(rA * 128 + cA * 2)) ^ lm;
    const int rB = (lane & 7) + 8 * ((lane >> 3) & 1);
    const int cB = e0 + 8 * (lane >> 4);
    const uint32_t swB0 = ((uint32_t)(rB * 128 + cB * 2)) ^ lm;
    const uint32_t swB1 = ((uint32_t)(rB * 128 + (cB + 16) * 2)) ^ lm;

    float acc[4][4];
#pragma unroll
    for (int i = 0; i < 4; i++)
#pragma unroll
        for (int j = 0; j < 4; j++) acc[i][j] = 0.f;

    float nacc[16];
#pragma unroll
    for (int i = 0; i < 16; i++) nacc[i] = 0.f;

    const float* mb = mem + (size_t)b * NMEM * DMEM;

    float4 m4[4], a4[4];
    auto ldg_chunk = [&](int ch) {
        const float* pm = mb   + ((size_t)ch * 64 + n1) * DMEM + dg;
        const float* pa = addr + ((size_t)ch * 64 + n1) * DMEM + dg;
#pragma unroll
        for (int j = 0; j < 4; j++) {
            m4[j] = *(const float4*)(pm + 4 * j);
            a4[j] = *(const float4*)(pa + 4 * j);
        }
    };

    ldg_chunk(0);

    for (int ch = 0; ch < NMEM / 64; ch++) {
        // ---- convert + store tiles (single buffer; safe: store after compute sync) ----
        {
            float mv[16], kv[16];
#pragma unroll
            for (int j = 0; j < 4; j++) {
                mv[4*j+0] = m4[j].x; mv[4*j+1] = m4[j].y;
                mv[4*j+2] = m4[j].z; mv[4*j+3] = m4[j].w;
                kv[4*j+0] = fmaxf(m4[j].x + a4[j].x, 0.f);
                kv[4*j+1] = fmaxf(m4[j].y + a4[j].y, 0.f);
                kv[4*j+2] = fmaxf(m4[j].z + a4[j].z, 0.f);
                kv[4*j+3] = fmaxf(m4[j].w + a4[j].w, 0.f);
            }
#pragma unroll
            for (int i = 0; i < 16; i++) nacc[i] += kv[i];
#pragma unroll
            for (int g = 0; g < 2; g++) {
                uint32_t kh[4], kl[4], mh[4], ml[4];
#pragma unroll
                for (int p = 0; p < 4; p++) {
                    split2(make_float2(kv[8*g+2*p], kv[8*g+2*p+1]), kh[p], kl[p]);
                    split2(make_float2(mv[8*g+2*p], mv[8*g+2*p+1]), mh[p], ml[p]);
                }
                uint32_t sw = g ? sw1 : sw0;
                *(uint4*)(sm + KH + sw) = make_uint4(kh[0], kh[1], kh[2], kh[3]);
                *(uint4*)(sm + KL + sw) = make_uint4(kl[0], kl[1], kl[2], kl[3]);
                *(uint4*)(sm + MH + sw) = make_uint4(mh[0], mh[1], mh[2], mh[3]);
                *(uint4*)(sm + ML + sw) = make_uint4(ml[0], ml[1], ml[2], ml[3]);
            }
        }
        __syncthreads();

        if (ch + 1 < NMEM / 64) ldg_chunk(ch + 1);   // overlap LDG with mma

        // ---- mma phase: 4 ksteps x (2 A-ldsm + 4 B-ldsm + 12 mma) ----
#pragma unroll
        for (int ks = 0; ks < 4; ks++) {
            const uint32_t ko = 2048u * ks;
            uint32_t ah[4], al[4], bh0[4], bh1[4], bl0[4], bl1[4];
            ldsm4t(ah,  sb + KH + swA + ko);
            ldsm4t(al,  sb + KL + swA + ko);
            ldsm4t(bh0, sb + MH + swB0 + ko);
            ldsm4t(bh1, sb + MH + swB1 + ko);
            ldsm4t(bl0, sb + ML + swB0 + ko);
            ldsm4t(bl1, sb + ML + swB1 + ko);
            // hi*hi
            mma16816(acc[0], ah, bh0[0], bh0[1]);
            mma16816(acc[1], ah, bh0[2], bh0[3]);
            mma16816(acc[2], ah, bh1[0], bh1[1]);
            mma16816(acc[3], ah, bh1[2], bh1[3]);
            // hi*lo
            mma16816(acc[0], ah, bl0[0], bl0[1]);
            mma16816(acc[1], ah, bl0[2], bl0[3]);
            mma16816(acc[2], ah, bl1[0], bl1[1]);
            mma16816(acc[3], ah, bl1[2], bl1[3]);
            // lo*hi
            mma16816(acc[0], al, bh0[0], bh0[1]);
            mma16816(acc[1], al, bh0[2], bh0[3]);
            mma16816(acc[2], al, bh1[0], bh1[1]);
            mma16816(acc[3], al, bh1[2], bh1[3]);
        }
        __syncthreads();
    }

    // ---- write matrix: C frag layout row=lane>>2(+8), col=(lane&3)*2 ----
    {
        float* om = g_mat + (size_t)b * DMEM * DMEM;
        int r0 = m0 + (lane >> 2);
        int c0 = e0 + (lane & 3) * 2;
#pragma unroll
        for (int j = 0; j < 4; j++) {
            int c = c0 + 8 * j;
            *(float2*)(om + (size_t)r0 * DMEM + c)       = make_float2(acc[j][0], acc[j][1]);
            *(float2*)(om + (size_t)(r0 + 8) * DMEM + c) = make_float2(acc[j][2], acc[j][3]);
        }
    }

    // ---- normalizer reduce via smem scratch (tiles dead; stride 65 = conflict-free) ----
    float* scr = (float*)sm;
#pragma unroll
    for (int i = 0; i < 16; i++) scr[n1 * 65 + dg + i] = nacc[i];
    __syncthreads();
    if (tid < DMEM) {
        float s = 0.f;
#pragma unroll 8
        for (int n = 0; n < 64; n++) s += scr[n * 65 + tid];
        g_norm[b * DMEM + tid] = s;
    }
}

// ============================================================
// HMMA split-K NT GEMM: P[kt] = A[128,1024] @ W[1024,1024]^T chunk
// grid (16 n-tiles, 8 k-splits) = 128 blocks. Block: m=128 full, n=64,
// k-chunk 128. A row-major and W row-major need NO transposes.
// smem: Ah/Al 32KB each, Wh/Wl 16KB each (96KB, dynamic).
// ============================================================
#define GA_H 0
#define GA_L 32768
#define GW_H 65536
#define GW_L 81920
#define G_SMEM 98304

__global__ __launch_bounds__(256, 1) void gemm_mma(
    const float* __restrict__ A_ext, const float* __restrict__ W, int mode)
{
    extern __shared__ __align__(1024) char sm[];
    const uint32_t sb = smem_u32(sm);
    const float* A = mode ? g_attn : A_ext;

    const int tid = threadIdx.x, lane = tid & 31, w = tid >> 5;
    const int bn = blockIdx.x * 64;
    const int kc0 = blockIdx.y * 128;

    // ---- convert A chunk [128 x 128] ----
#pragma unroll
    for (int i = 0; i < 8; i++) {
        int item = tid + 256 * i;
        int row = item >> 4, c8 = item & 15;
        const float* p = A + (size_t)row * DMODEL + kc0 + c8 * 8;
        float4 f0 = *(const float4*)p, f1 = *(const float4*)(p + 4);
        uint32_t h[4], l[4];
        split2(make_float2(f0.x, f0.y), h[0], l[0]);
        split2(make_float2(f0.z, f0.w), h[1], l[1]);
        split2(make_float2(f1.x, f1.y), h[2], l[2]);
        split2(make_float2(f1.z, f1.w), h[3], l[3]);
        uint32_t off = (uint32_t)(row * 256 + c8 * 16);
        uint32_t sw = off ^ ((off >> 4) & 0x70);
        *(uint4*)(sm + GA_H + sw) = make_uint4(h[0], h[1], h[2], h[3]);
        *(uint4*)(sm + GA_L + sw) = make_uint4(l[0], l[1], l[2], l[3]);
    }
    // ---- convert W chunk [64 x 128] ----
#pragma unroll
    for (int i = 0; i < 4; i++) {
        int item = tid + 256 * i;
        int row = item >> 4, c8 = item & 15;
        const float* p = W + (size_t)(bn + row) * DMODEL + kc0 + c8 * 8;
        float4 f0 = *(const float4*)p, f1 = *(const float4*)(p + 4);
        uint32_t h[4], l[4];
        split2(make_float2(f0.x, f0.y), h[0], l[0]);
        split2(make_float2(f0.z, f0.w), h[1], l[1]);
        split2(make_float2(f1.x, f1.y), h[2], l[2]);
        split2(make_float2(f1.z, f1.w), h[3], l[3]);
        uint32_t off = (uint32_t)(row * 256 + c8 * 16);
        uint32_t sw = off ^ ((off >> 4) & 0x70);
        *(uint4*)(sm + GW_H + sw) = make_uint4(h[0], h[1], h[2], h[3]);
        *(uint4*)(sm + GW_L + sw) = make_uint4(l[0], l[1], l[2], l[3]);
    }
    __syncthreads();

    // ---- mma: warp w owns m rows 16w, all 64 n ----
    const int m0 = w * 16;
    float acc[8][4];
#pragma unroll
    for (int i = 0; i < 8; i++)
#pragma unroll
        for (int j = 0; j < 4; j++) acc[i][j] = 0.f;

    const int rA = (lane & 7) + 8 * ((lane >> 3) & 1);
    const uint32_t baseA = (uint32_t)((m0 + rA) * 256 + (lane >> 4) * 16);
    const uint32_t maskA = (uint32_t)(lane & 7) << 4;
    const int rBl = (lane & 7) + 8 * (lane >> 4);
    const uint32_t hB = ((uint32_t)(lane >> 3) & 1) * 16;
    const uint32_t maskB = (uint32_t)(lane & 7) << 4;

#pragma unroll
    for (int ks = 0; ks < 8; ks++) {
        uint32_t swAa = (baseA + ks * 32) ^ maskA;
        uint32_t ah[4], al[4];
        ldsm4(ah, sb + GA_H + swAa);
        ldsm4(al, sb + GA_L + swAa);
#pragma unroll
        for (int j = 0; j < 4; j++) {
            uint32_t offB = (uint32_t)((16 * j + rBl) * 256 + ks * 32) + hB;
            uint32_t swB = offB ^ maskB;
            uint32_t wh[4], wl[4];
            ldsm4(wh, sb + GW_H + swB);
            ldsm4(wl, sb + GW_L + swB);
            mma16816(acc[2*j],     ah, wh[0], wh[1]);
            mma16816(acc[2*j + 1], ah, wh[2], wh[3]);
            mma16816(acc[2*j],     ah, wl[0], wl[1]);
            mma16816(acc[2*j + 1], ah, wl[2], wl[3]);
            mma16816(acc[2*j],     al, wh[0], wh[1]);
            mma16816(acc[2*j + 1], al, wh[2], wh[3]);
        }
    }

    // ---- write partials ----
    float* P = g_gp + (size_t)blockIdx.y * (Bn * DMODEL);
    int r0 = m0 + (lane >> 2);
    int c0 = bn + (lane & 3) * 2;
#pragma unroll
    for (int jj = 0; jj < 8; jj++) {
        int c = c0 + 8 * jj;
        *(float2*)(P + (size_t)r0 * DMODEL + c)       = make_float2(acc[jj][0], acc[jj][1]);
        *(float2*)(P + (size_t)(r0 + 8) * DMODEL + c) = make_float2(acc[jj][2], acc[jj][3]);
    }
}

// reduce 8 split-K partials + bias (+relu for mode 0)
__global__ __launch_bounds__(256) void gemm_reduce(
    const float* __restrict__ bias, float* __restrict__ C_ext, int mode)
{
    int idx = blockIdx.x * 256 + threadIdx.x;
    float v = bias[idx & (DMODEL - 1)];
#pragma unroll
    for (int s = 0; s < 8; s++) v += g_gp[(size_t)s * Bn * DMODEL + idx];
    if (mode == 0) g_qa[idx] = fmaxf(v, 0.f);
    else           C_ext[idx] = v;
}

// ============================================================
// Stage 2 read: one block per batch, matrix smem-resident.
// ============================================================
__global__ __launch_bounds__(256) void attn_read_kernel()
{
    __shared__ float s_mat[DMEM * DMEM];
    __shared__ float s_q[NH * DMEM];
    __shared__ float s_n[DMEM];
    __shared__ float s_den[NH];

    const int b = blockIdx.x;
    const int tid = threadIdx.x;

    {
        float4* dst = (float4*)s_mat;
        const float4* src = (const float4*)(g_mat + (size_t)b * DMEM * DMEM);
#pragma unroll
        for (int i = 0; i < 4; i++) dst[tid + 256 * i] = src[tid + 256 * i];
        ((float4*)s_q)[tid] = ((const float4*)(g_qa + (size_t)b * DMODEL))[tid];
        if (tid < 16) ((float4*)s_n)[tid] = ((const float4*)(g_norm + b * DMEM))[tid];
    }
    __syncthreads();

    if (tid < NH) {
        float s = 0.f;
#pragma unroll 8
        for (int d = 0; d < DMEM; d++) s += s_q[tid * DMEM + d] * s_n[d];
        s_den[tid] = s + 1e-5f;
    }
    __syncthreads();

    const int e = tid & 63;
    const int hq = tid >> 6;
#pragma unroll
    for (int i = 0; i < 4; i++) {
        int h = hq * 4 + i;
        float acc = 0.f;
#pragma unroll 8
        for (int d = 0; d < DMEM; d++) acc += s_q[h * DMEM + d] * s_mat[d * DMEM + e];
        g_attn[(size_t)b * DMODEL + h * DMEM + e] = acc / s_den[h];
    }
}

// ============================================================
extern "C" void kernel_launch(void* const* d_in, const int* in_sizes, int n_in,
                              void* d_out, int out_size)
{
    (void)in_sizes; (void)n_in; (void)out_size;
    const float* query     = (const float*)d_in[0];
    const float* addresses = (const float*)d_in[1];
    const float* memories  = (const float*)d_in[2];
    const float* Wq        = (const float*)d_in[3];
    const float* bq        = (const float*)d_in[4];
    const float* Wm        = (const float*)d_in[5];
    const float* bm        = (const float*)d_in[6];
    float* out = (float*)d_out;

    static bool attr_set = false;
    if (!attr_set) {
        cudaFuncSetAttribute(gemm_mma, cudaFuncAttributeMaxDynamicSharedMemorySize, G_SMEM);
        attr_set = true;
    }

    // qa = relu(query @ Wq^T + bq)
    gemm_mma<<<dim3(16, 8), 256, G_SMEM>>>(query, Wq, 0);
    gemm_reduce<<<512, 256>>>(bq, nullptr, 0);
    // matrix / normalizer
    stage1_mma<<<Bn, 256, S1_SMEM>>>(memories, addresses);
    // attn
    attn_read_kernel<<<Bn, 256>>>();
    // out = attn @ Wm^T + bm
    gemm_mma<<<dim3(16, 8), 256, G_SMEM>>>(nullptr, Wm, 1);
    gemm_reduce<<<512, 256>>>(bm, out, 1);
}

// round 11
// speedup vs baseline: 2.5897x; 1.2431x over previous
#include <cuda_runtime.h>
#include <cuda_bf16.h>
#include <cstdint>

#define Bn      128
#define DMODEL  1024
#define DMEM    64
#define NH      16
#define NMEM    4096

// ================= helpers =================
__device__ __forceinline__ uint32_t smem_u32(const void* p) {
    uint32_t a;
    asm("{ .reg .u64 t; cvta.to.shared.u64 t, %1; cvt.u32.u64 %0, t; }"
        : "=r"(a) : "l"(p));
    return a;
}
__device__ __forceinline__ void ldsm4(uint32_t* r, uint32_t a) {
    asm volatile("ldmatrix.sync.aligned.m8n8.x4.shared.b16 {%0,%1,%2,%3}, [%4];"
                 : "=r"(r[0]), "=r"(r[1]), "=r"(r[2]), "=r"(r[3]) : "r"(a));
}
__device__ __forceinline__ void ldsm4t(uint32_t* r, uint32_t a) {
    asm volatile("ldmatrix.sync.aligned.m8n8.x4.trans.shared.b16 {%0,%1,%2,%3}, [%4];"
                 : "=r"(r[0]), "=r"(r[1]), "=r"(r[2]), "=r"(r[3]) : "r"(a));
}
__device__ __forceinline__ void mma16816(float* c, const uint32_t* a,
                                         uint32_t b0, uint32_t b1) {
    asm volatile(
        "mma.sync.aligned.m16n8k16.row.col.f32.bf16.bf16.f32 "
        "{%0,%1,%2,%3}, {%4,%5,%6,%7}, {%8,%9}, {%0,%1,%2,%3};"
        : "+f"(c[0]), "+f"(c[1]), "+f"(c[2]), "+f"(c[3])
        : "r"(a[0]), "r"(a[1]), "r"(a[2]), "r"(a[3]), "r"(b0), "r"(b1));
}
__device__ __forceinline__ unsigned b2u(__nv_bfloat162 v) {
    return *reinterpret_cast<unsigned*>(&v);
}
__device__ __forceinline__ void split2(float2 f, uint32_t& hi, uint32_t& lo) {
    __nv_bfloat162 h = __float22bfloat162_rn(f);
    float2 hf = __bfloat1622float2(h);
    __nv_bfloat162 l = __float22bfloat162_rn(make_float2(f.x - hf.x, f.y - hf.y));
    hi = b2u(h);
    lo = b2u(l);
}

// ================= scratch =================
__device__ float g_qa[Bn * DMODEL];
__device__ float g_attn[Bn * DMODEL];
__device__ float g_gp[8 * Bn * DMODEL];      // split-K partials (4 MB)

// ============================================================
// Stage 1 + attn read, fused (HMMA). Per batch b:
//   matrix[d][e] = sum_n relu(mem+addr)[n][d] * mem[n][e]   (smem only)
//   norm[d]      = sum_n k[n][d]
//   attn[h][e]   = (qa[h] . matrix[:,e]) / (qa[h] . norm + 1e-5)
// 512 threads = 16 warps: (wd 0..3) x (we 0..1) x (wk 0..1 k-split).
// Double-buffered bf16 tiles [n=64][feat=64] (kh,kl,mh,ml), XOR-swizzled.
// ============================================================
#define S1_SMEM 65536

__global__ __launch_bounds__(512, 1) void stage1_fused(
    const float* __restrict__ mem, const float* __restrict__ addr)
{
    extern __shared__ __align__(1024) char sm[];
    const uint32_t sb = smem_u32(sm);
    const int b = blockIdx.x, tid = threadIdx.x;
    const int lane = tid & 31, w = tid >> 5;

    // tile offsets within one buffer; buffer stride 32768
    const uint32_t KH = 0, KL = 8192, MH = 16384, ML = 24576;

    // ---- conversion mapping: thread -> (n row, 8-float d group) ----
    const int n1 = tid >> 3;                 // 0..63
    const int dg = (tid & 7) << 3;           // float col base, 0..56
    const uint32_t swc = ((uint32_t)(n1 * 128 + dg * 2)) ^ ((uint32_t)(n1 & 7) << 4);

    // ---- mma mapping ----
    const int wd = w & 3, we = (w >> 2) & 1, wk = w >> 3;
    const int m0 = wd * 16;                  // d rows
    const int e0 = we * 32;                  // e cols
    const uint32_t lm = (uint32_t)(lane & 7) << 4;
    const int rA = (lane & 7) + 8 * (lane >> 4);
    const int cA = m0 + 8 * ((lane >> 3) & 1);
    const uint32_t swA = ((uint32_t)(rA * 128 + cA * 2)) ^ lm;
    const int rB = (lane & 7) + 8 * ((lane >> 3) & 1);
    const int cB = e0 + 8 * (lane >> 4);
    const uint32_t swB0 = ((uint32_t)(rB * 128 + cB * 2)) ^ lm;
    const uint32_t swB1 = ((uint32_t)(rB * 128 + (cB + 16) * 2)) ^ lm;

    float acc[4][4];
#pragma unroll
    for (int i = 0; i < 4; i++)
#pragma unroll
        for (int j = 0; j < 4; j++) acc[i][j] = 0.f;

    float nacc[8];
#pragma unroll
    for (int i = 0; i < 8; i++) nacc[i] = 0.f;

    const float* mb = mem + (size_t)b * NMEM * DMEM;

    float4 m4[2], a4[2];
    auto ldg_chunk = [&](int ch) {
        const float* pm = mb   + ((size_t)ch * 64 + n1) * DMEM + dg;
        const float* pa = addr + ((size_t)ch * 64 + n1) * DMEM + dg;
        m4[0] = *(const float4*)pm;
        m4[1] = *(const float4*)(pm + 4);
        a4[0] = *(const float4*)pa;
        a4[1] = *(const float4*)(pa + 4);
    };
    auto cvt_store = [&](int buf) {
        float mv[8], kv[8];
#pragma unroll
        for (int j = 0; j < 2; j++) {
            mv[4*j+0] = m4[j].x; mv[4*j+1] = m4[j].y;
            mv[4*j+2] = m4[j].z; mv[4*j+3] = m4[j].w;
            kv[4*j+0] = fmaxf(m4[j].x + a4[j].x, 0.f);
            kv[4*j+1] = fmaxf(m4[j].y + a4[j].y, 0.f);
            kv[4*j+2] = fmaxf(m4[j].z + a4[j].z, 0.f);
            kv[4*j+3] = fmaxf(m4[j].w + a4[j].w, 0.f);
        }
#pragma unroll
        for (int i = 0; i < 8; i++) nacc[i] += kv[i];
        uint32_t kh[4], kl[4], mh[4], ml[4];
#pragma unroll
        for (int p = 0; p < 4; p++) {
            split2(make_float2(kv[2*p], kv[2*p+1]), kh[p], kl[p]);
            split2(make_float2(mv[2*p], mv[2*p+1]), mh[p], ml[p]);
        }
        char* base = sm + buf * 32768;
        *(uint4*)(base + KH + swc) = make_uint4(kh[0], kh[1], kh[2], kh[3]);
        *(uint4*)(base + KL + swc) = make_uint4(kl[0], kl[1], kl[2], kl[3]);
        *(uint4*)(base + MH + swc) = make_uint4(mh[0], mh[1], mh[2], mh[3]);
        *(uint4*)(base + ML + swc) = make_uint4(ml[0], ml[1], ml[2], ml[3]);
    };

    ldg_chunk(0);
    cvt_store(0);
    __syncthreads();

    for (int ch = 0; ch < NMEM / 64; ch++) {
        const uint32_t tb = sb + (uint32_t)(ch & 1) * 32768;
        if (ch + 1 < NMEM / 64) ldg_chunk(ch + 1);

        // ---- mma: this warp handles ksteps {2*wk, 2*wk+1} ----
#pragma unroll
        for (int ks = 0; ks < 2; ks++) {
            const uint32_t ko = 2048u * (2 * wk + ks);
            uint32_t ah[4], al[4], bh0[4], bh1[4], bl0[4], bl1[4];
            ldsm4t(ah,  tb + KH + swA + ko);
            ldsm4t(al,  tb + KL + swA + ko);
            ldsm4t(bh0, tb + MH + swB0 + ko);
            ldsm4t(bh1, tb + MH + swB1 + ko);
            ldsm4t(bl0, tb + ML + swB0 + ko);
            ldsm4t(bl1, tb + ML + swB1 + ko);
            mma16816(acc[0], ah, bh0[0], bh0[1]);
            mma16816(acc[1], ah, bh0[2], bh0[3]);
            mma16816(acc[2], ah, bh1[0], bh1[1]);
            mma16816(acc[3], ah, bh1[2], bh1[3]);
            mma16816(acc[0], ah, bl0[0], bl0[1]);
            mma16816(acc[1], ah, bl0[2], bl0[3]);
            mma16816(acc[2], ah, bl1[0], bl1[1]);
            mma16816(acc[3], ah, bl1[2], bl1[3]);
            mma16816(acc[0], al, bh0[0], bh0[1]);
            mma16816(acc[1], al, bh0[2], bh0[3]);
            mma16816(acc[2], al, bh1[0], bh1[1]);
            mma16816(acc[3], al, bh1[2], bh1[3]);
        }

        if (ch + 1 < NMEM / 64) cvt_store((ch + 1) & 1);
        __syncthreads();
    }

    // ================= fused epilogue =================
    // smem reuse (all tiles dead): mat[64][66] @0, npart[64][66] @32768,
    // qa[16][64] @49664, norm[64] @53760, den[16] @54016
    float* s_mat = (float*)sm;
    float* s_np  = (float*)(sm + 32768);
    float* s_qa  = (float*)(sm + 49664);
    float* s_nr  = (float*)(sm + 53760);
    float* s_dn  = (float*)(sm + 54016);

    const int cr0 = m0 + (lane >> 2);
    const int cc0 = e0 + (lane & 3) * 2;

    // step A: wk=0 accs -> mat; norm partials; qa copy
    if (wk == 0) {
#pragma unroll
        for (int j = 0; j < 4; j++) {
            int c = cc0 + 8 * j;
            s_mat[cr0 * 66 + c]           = acc[j][0];
            s_mat[cr0 * 66 + c + 1]       = acc[j][1];
            s_mat[(cr0 + 8) * 66 + c]     = acc[j][2];
            s_mat[(cr0 + 8) * 66 + c + 1] = acc[j][3];
        }
    }
#pragma unroll
    for (int i = 0; i < 8; i++) s_np[n1 * 66 + dg + i] = nacc[i];
    if (tid < 256)
        ((float4*)s_qa)[tid] = ((const float4*)(g_qa + (size_t)b * DMODEL))[tid];
    __syncthreads();

    // step B: wk=1 accs merge; norm reduce
    if (wk == 1) {
#pragma unroll
        for (int j = 0; j < 4; j++) {
            int c = cc0 + 8 * j;
            s_mat[cr0 * 66 + c]           += acc[j][0];
            s_mat[cr0 * 66 + c + 1]       += acc[j][1];
            s_mat[(cr0 + 8) * 66 + c]     += acc[j][2];
            s_mat[(cr0 + 8) * 66 + c + 1] += acc[j][3];
        }
    }
    if (tid < DMEM) {
        float s = 0.f;
#pragma unroll 8
        for (int n = 0; n < 64; n++) s += s_np[n * 66 + tid];
        s_nr[tid] = s;
    }
    __syncthreads();

    // step C: denominators
    if (tid < NH) {
        float s = 0.f;
#pragma unroll 8
        for (int d = 0; d < DMEM; d++) s += s_qa[tid * DMEM + d] * s_nr[d];
        s_dn[tid] = s + 1e-5f;
    }
    __syncthreads();

    // step D: attn = qa @ mat / den   (each thread: heads h0 and h0+8, col e)
    {
        const int e = tid & 63;
        const int h0 = tid >> 6;          // 0..7
        float a0 = 0.f, a1 = 0.f;
#pragma unroll 8
        for (int d = 0; d < DMEM; d++) {
            float mv = s_mat[d * 66 + e];
            a0 += s_qa[h0 * DMEM + d] * mv;
            a1 += s_qa[(h0 + 8) * DMEM + d] * mv;
        }
        float* oa = g_attn + (size_t)b * DMODEL;
        oa[h0 * DMEM + e]       = a0 / s_dn[h0];
        oa[(h0 + 8) * DMEM + e] = a1 / s_dn[h0 + 8];
    }
}

// ============================================================
// HMMA split-K NT GEMM (known-good from R10)
// ============================================================
#define GA_H 0
#define GA_L 32768
#define GW_H 65536
#define GW_L 81920
#define G_SMEM 98304

__global__ __launch_bounds__(256, 1) void gemm_mma(
    const float* __restrict__ A_ext, const float* __restrict__ W, int mode)
{
    extern __shared__ __align__(1024) char sm[];
    const uint32_t sb = smem_u32(sm);
    const float* A = mode ? g_attn : A_ext;

    const int tid = threadIdx.x, lane = tid & 31, w = tid >> 5;
    const int bn = blockIdx.x * 64;
    const int kc0 = blockIdx.y * 128;

#pragma unroll
    for (int i = 0; i < 8; i++) {
        int item = tid + 256 * i;
        int row = item >> 4, c8 = item & 15;
        const float* p = A + (size_t)row * DMODEL + kc0 + c8 * 8;
        float4 f0 = *(const float4*)p, f1 = *(const float4*)(p + 4);
        uint32_t h[4], l[4];
        split2(make_float2(f0.x, f0.y), h[0], l[0]);
        split2(make_float2(f0.z, f0.w), h[1], l[1]);
        split2(make_float2(f1.x, f1.y), h[2], l[2]);
        split2(make_float2(f1.z, f1.w), h[3], l[3]);
        uint32_t off = (uint32_t)(row * 256 + c8 * 16);
        uint32_t sw = off ^ ((off >> 4) & 0x70);
        *(uint4*)(sm + GA_H + sw) = make_uint4(h[0], h[1], h[2], h[3]);
        *(uint4*)(sm + GA_L + sw) = make_uint4(l[0], l[1], l[2], l[3]);
    }
#pragma unroll
    for (int i = 0; i < 4; i++) {
        int item = tid + 256 * i;
        int row = item >> 4, c8 = item & 15;
        const float* p = W + (size_t)(bn + row) * DMODEL + kc0 + c8 * 8;
        float4 f0 = *(const float4*)p, f1 = *(const float4*)(p + 4);
        uint32_t h[4], l[4];
        split2(make_float2(f0.x, f0.y), h[0], l[0]);
        split2(make_float2(f0.z, f0.w), h[1], l[1]);
        split2(make_float2(f1.x, f1.y), h[2], l[2]);
        split2(make_float2(f1.z, f1.w), h[3], l[3]);
        uint32_t off = (uint32_t)(row * 256 + c8 * 16);
        uint32_t sw = off ^ ((off >> 4) & 0x70);
        *(uint4*)(sm + GW_H + sw) = make_uint4(h[0], h[1], h[2], h[3]);
        *(uint4*)(sm + GW_L + sw) = make_uint4(l[0], l[1], l[2], l[3]);
    }
    __syncthreads();

    const int m0 = w * 16;
    float acc[8][4];
#pragma unroll
    for (int i = 0; i < 8; i++)
#pragma unroll
        for (int j = 0; j < 4; j++) acc[i][j] = 0.f;

    const int rA = (lane & 7) + 8 * ((lane >> 3) & 1);
    const uint32_t baseA = (uint32_t)((m0 + rA) * 256 + (lane >> 4) * 16);
    const uint32_t maskA = (uint32_t)(lane & 7) << 4;
    const int rBl = (lane & 7) + 8 * (lane >> 4);
    const uint32_t hB = ((uint32_t)(lane >> 3) & 1) * 16;
    const uint32_t maskB = (uint32_t)(lane & 7) << 4;

#pragma unroll
    for (int ks = 0; ks < 8; ks++) {
        uint32_t swAa = (baseA + ks * 32) ^ maskA;
        uint32_t ah[4], al[4];
        ldsm4(ah, sb + GA_H + swAa);
        ldsm4(al, sb + GA_L + swAa);
#pragma unroll
        for (int j = 0; j < 4; j++) {
            uint32_t offB = (uint32_t)((16 * j + rBl) * 256 + ks * 32) + hB;
            uint32_t swB = offB ^ maskB;
            uint32_t wh[4], wl[4];
            ldsm4(wh, sb + GW_H + swB);
            ldsm4(wl, sb + GW_L + swB);
            mma16816(acc[2*j],     ah, wh[0], wh[1]);
            mma16816(acc[2*j + 1], ah, wh[2], wh[3]);
            mma16816(acc[2*j],     ah, wl[0], wl[1]);
            mma16816(acc[2*j + 1], ah, wl[2], wl[3]);
            mma16816(acc[2*j],     al, wh[0], wh[1]);
            mma16816(acc[2*j + 1], al, wh[2], wh[3]);
        }
    }

    float* P = g_gp + (size_t)blockIdx.y * (Bn * DMODEL);
    int r0 = m0 + (lane >> 2);
    int c0 = bn + (lane & 3) * 2;
#pragma unroll
    for (int jj = 0; jj < 8; jj++) {
        int c = c0 + 8 * jj;
        *(float2*)(P + (size_t)r0 * DMODEL + c)       = make_float2(acc[jj][0], acc[jj][1]);
        *(float2*)(P + (size_t)(r0 + 8) * DMODEL + c) = make_float2(acc[jj][2], acc[jj][3]);
    }
}

__global__ __launch_bounds__(256) void gemm_reduce(
    const float* __restrict__ bias, float* __restrict__ C_ext, int mode)
{
    int idx = blockIdx.x * 256 + threadIdx.x;
    float v = bias[idx & (DMODEL - 1)];
#pragma unroll
    for (int s = 0; s < 8; s++) v += g_gp[(size_t)s * Bn * DMODEL + idx];
    if (mode == 0) g_qa[idx] = fmaxf(v, 0.f);
    else           C_ext[idx] = v;
}

// ============================================================
extern "C" void kernel_launch(void* const* d_in, const int* in_sizes, int n_in,
                              void* d_out, int out_size)
{
    (void)in_sizes; (void)n_in; (void)out_size;
    const float* query     = (const float*)d_in[0];
    const float* addresses = (const float*)d_in[1];
    const float* memories  = (const float*)d_in[2];
    const float* Wq        = (const float*)d_in[3];
    const float* bq        = (const float*)d_in[4];
    const float* Wm        = (const float*)d_in[5];
    const float* bm        = (const float*)d_in[6];
    float* out = (float*)d_out;

    cudaFuncSetAttribute(gemm_mma, cudaFuncAttributeMaxDynamicSharedMemorySize, G_SMEM);
    cudaFuncSetAttribute(stage1_fused, cudaFuncAttributeMaxDynamicSharedMemorySize, S1_SMEM);

    // qa = relu(query @ Wq^T + bq)
    gemm_mma<<<dim3(16, 8), 256, G_SMEM>>>(query, Wq, 0);
    gemm_reduce<<<512, 256>>>(bq, nullptr, 0);
    // matrix + normalizer + attn (fused)
    stage1_fused<<<Bn, 512, S1_SMEM>>>(memories, addresses);
    // out = attn @ Wm^T + bm
    gemm_mma<<<dim3(16, 8), 256, G_SMEM>>>(nullptr, Wm, 1);
    gemm_reduce<<<512, 256>>>(bm, out, 1);
}